// round 5
// baseline (speedup 1.0000x reference)
#include <cuda_runtime.h>
#include <cstdint>

#define CC 96
#define HH 256
#define WW 256
#define KK 7

__device__ __forceinline__ void fma2(unsigned long long &d,
                                     unsigned long long a,
                                     unsigned long long b) {
    asm("fma.rn.f32x2 %0, %1, %2, %0;" : "+l"(d) : "l"(a), "l"(b));
}
__device__ __forceinline__ unsigned long long pk2(float lo, float hi) {
    return (unsigned long long)__float_as_uint(lo) |
           ((unsigned long long)__float_as_uint(hi) << 32);
}
__device__ __forceinline__ void upk2(unsigned long long v, float &lo, float &hi) {
    lo = __uint_as_float((unsigned int)(v & 0xffffffffull));
    hi = __uint_as_float((unsigned int)(v >> 32));
}

// blockDim=(64,2), grid=(1,2,nimg). Thread: 4 cols (float4), 64-row strip.
// Fast path (r < 5/3): folded 11-tap integer-offset conv (span -5..+5).
//   H conv: 16-slot register ring, prefetch 3 rows ahead (y+8) to cover DRAM.
//   W conv: 14-col window (x4-5..x4+8), side loads same-iteration (L1 hits).
__global__ __launch_bounds__(128) void caxial_kernel(const float* __restrict__ x,
                                                     const float* __restrict__ wh,
                                                     const float* __restrict__ ww,
                                                     const float* __restrict__ rp,
                                                     float* __restrict__ out) {
    const int c  = blockIdx.z % CC;
    const int tx = threadIdx.x;                               // 0..63
    const int strip = blockIdx.y * 2 + threadIdx.y;           // 0..3
    const int x4 = tx * 4;
    const int y0 = strip * 64;
    const float* xc = x   + (size_t)blockIdx.z * (HH * WW);
    float*       oc = out + (size_t)blockIdx.z * (HH * WW);

    float rv = rp[0];
    if (rv < 1.0f) rv = 1.0f;

    float whv[KK], wwv[KK], fri[KK];
    int   k0i[KK];
    #pragma unroll
    for (int i = 0; i < KK; i++) {
        float ofr = (float)(i - 3) * rv;
        float fl  = floorf(ofr);
        k0i[i] = (int)fl + 5;                 // index base dr = k - 5
        fri[i] = ofr - fl;
        whv[i] = wh[c * KK + i];
        wwv[i] = ww[c * KK + i];
    }
    // fast: all taps (incl. +1 bilinear partner) fall in k = 0..10
    const bool fast = (k0i[0] >= 0) && (k0i[KK - 1] + 1 <= 10);

    if (fast) {
        // Fold 7 bilinear taps into 11 integer-offset weights (dc/dr = k - 5)
        unsigned long long cwh2[11];
        float cww[11];
        #pragma unroll
        for (int k = 0; k < 11; k++) {
            float sh = 0.f, sw = 0.f;
            #pragma unroll
            for (int i = 0; i < KK; i++) {
                if (k0i[i] == k)     { sh += whv[i] * (1.f - fri[i]); sw += wwv[i] * (1.f - fri[i]); }
                if (k0i[i] + 1 == k) { sh += whv[i] * fri[i];         sw += wwv[i] * fri[i]; }
            }
            cwh2[k] = pk2(sh, sh);
            cww[k]  = sw;
        }

        // Register ring: 16 rows, one float4 each. slot(row) = row & 15 (y0 % 16 == 0).
        // Prologue: rows y0-5 .. y0+7 (prefetch depth 3).
        ulonglong2 ring[16];
        #pragma unroll
        for (int t = -5; t <= 7; t++) {
            int row = y0 + t;
            ulonglong2 v = make_ulonglong2(0ull, 0ull);
            if (row >= 0)   // row < HH always true in prologue (y0 <= 192, t <= 7)
                v = *reinterpret_cast<const ulonglong2*>(xc + (size_t)row * WW + x4);
            ring[(t + 16) & 15] = v;
        }

        // Side-load predicates: window cols x4-5 .. x4+8
        const bool eL2 = (x4 >= 8);           // col  x4-5         (LDG.32)
        const bool eL1 = (x4 >= 4);           // cols x4-4..x4-1   (LDG.128)
        const bool eR1 = (x4 <= WW - 8);      // cols x4+4..x4+7   (LDG.128)
        const bool eR2 = (x4 <= WW - 12);     // col  x4+8         (LDG.32)
        const float4 z4 = make_float4(0.f, 0.f, 0.f, 0.f);

        #pragma unroll 1
        for (int half = 0; half < 4; half++) {
            int ybase = y0 + half * 16;
            #pragma unroll
            for (int u = 0; u < 16; u++) {
                int y = ybase + u;

                // Ring prefetch: row y+8 into slot (u+8)&15 (first use 3 iters out)
                {
                    int row = y + 8;
                    ulonglong2 v = make_ulonglong2(0ull, 0ull);
                    if (row < HH)
                        v = *reinterpret_cast<const ulonglong2*>(xc + (size_t)row * WW + x4);
                    ring[(u + 8) & 15] = v;
                }

                // Side loads for row y (issued early; consumed after H conv)
                const float* rowp = xc + (size_t)y * WW;
                float  sl = eL2 ? rowp[x4 - 5] : 0.f;
                float4 l1 = eL1 ? *reinterpret_cast<const float4*>(rowp + x4 - 4) : z4;
                float4 r1 = eR1 ? *reinterpret_cast<const float4*>(rowp + x4 + 4) : z4;
                float  sr = eR2 ? rowp[x4 + 8] : 0.f;

                ulonglong2 ctr = ring[u & 15];       // row y, cols x4..x4+3
                float c0, c1, c2, c3;
                upk2(ctr.x, c0, c1);
                upk2(ctr.y, c2, c3);

                // identity + H conv (packed f32x2 FMAs), taps dr = k-5
                unsigned long long acc01 = ctr.x;
                unsigned long long acc23 = ctr.y;
                #pragma unroll
                for (int k = 0; k < 11; k++) {       // row y + (k-5)
                    ulonglong2 rv2 = ring[(u + k + 11) & 15];
                    fma2(acc01, cwh2[k], rv2.x);
                    fma2(acc23, cwh2[k], rv2.y);
                }
                float a0, a1, a2, a3;
                upk2(acc01, a0, a1);
                upk2(acc23, a2, a3);

                // W conv: win[m] = col (x4 - 5 + m), m = 0..13
                float win[14];
                win[0]  = sl;
                win[1]  = l1.x; win[2]  = l1.y; win[3]  = l1.z; win[4]  = l1.w;
                win[5]  = c0;   win[6]  = c1;   win[7]  = c2;   win[8]  = c3;
                win[9]  = r1.x; win[10] = r1.y; win[11] = r1.z; win[12] = r1.w;
                win[13] = sr;
                #pragma unroll
                for (int k = 0; k < 11; k++) {       // col (x4+j) + (k-5) = win[k+j]
                    float w = cww[k];
                    a0 += w * win[k];
                    a1 += w * win[k + 1];
                    a2 += w * win[k + 2];
                    a3 += w * win[k + 3];
                }

                __stcs(reinterpret_cast<float4*>(oc + (size_t)y * WW + x4),
                       make_float4(a0, a1, a2, a3));
            }
        }
    } else {
        // Generic path: direct 7-tap bilinear gather along both axes.
        #pragma unroll 1
        for (int yy = 0; yy < 64; yy++) {
            int y = y0 + yy;
            float acc[4];
            #pragma unroll
            for (int j = 0; j < 4; j++) acc[j] = xc[(size_t)y * WW + x4 + j];
            #pragma unroll
            for (int i = 0; i < KK; i++) {
                int   d  = k0i[i] - 5;
                float fr = fri[i];
                int r0 = y + d, r1 = r0 + 1;
                #pragma unroll
                for (int j = 0; j < 4; j++) {
                    int col = x4 + j;
                    float s0 = (r0 >= 0 && r0 < HH) ? xc[(size_t)r0 * WW + col] : 0.f;
                    float s1 = (r1 >= 0 && r1 < HH) ? xc[(size_t)r1 * WW + col] : 0.f;
                    acc[j] += whv[i] * (s0 * (1.f - fr) + s1 * fr);
                    int c0i = col + d, c1i = c0i + 1;
                    float t0 = (c0i >= 0 && c0i < WW) ? xc[(size_t)y * WW + c0i] : 0.f;
                    float t1 = (c1i >= 0 && c1i < WW) ? xc[(size_t)y * WW + c1i] : 0.f;
                    acc[j] += wwv[i] * (t0 * (1.f - fr) + t1 * fr);
                }
            }
            #pragma unroll
            for (int j = 0; j < 4; j++) oc[(size_t)y * WW + x4 + j] = acc[j];
        }
    }
}

extern "C" void kernel_launch(void* const* d_in, const int* in_sizes, int n_in,
                              void* d_out, int out_size) {
    const float* x  = (const float*)d_in[0];
    const float* wh = (const float*)d_in[1];
    const float* ww = (const float*)d_in[2];
    const float* r  = (const float*)d_in[3];
    float* out = (float*)d_out;

    int nimg = in_sizes[0] / (HH * WW);   // B*C = 768

    dim3 blk(64, 2, 1);
    dim3 grd(1, 2, nimg);
    caxial_kernel<<<grd, blk>>>(x, wh, ww, r, out);
}

// round 6
// speedup vs baseline: 1.4513x; 1.4513x over previous
#include <cuda_runtime.h>
#include <cstdint>

#define CC 96
#define HH 256
#define WW 256
#define KK 7

__device__ __forceinline__ void fma2(unsigned long long &d,
                                     unsigned long long a,
                                     unsigned long long b) {
    asm("fma.rn.f32x2 %0, %1, %2, %0;" : "+l"(d) : "l"(a), "l"(b));
}
__device__ __forceinline__ unsigned long long pk2(float lo, float hi) {
    return (unsigned long long)__float_as_uint(lo) |
           ((unsigned long long)__float_as_uint(hi) << 32);
}
__device__ __forceinline__ void upk2(unsigned long long v, float &lo, float &hi) {
    lo = __uint_as_float((unsigned int)(v & 0xffffffffull));
    hi = __uint_as_float((unsigned int)(v >> 32));
}

// blockDim=(64,2), grid=(1,2,nimg). Thread: 4 cols (float4), 64-row strip.
// Fast path (r < 5/3): folded 11-tap integer-offset conv (span -5..+5).
//   H conv: 12-slot register ring (slot = (row - y0 + 5) % 12, all static),
//           prefetch 1 row ahead of last tap (row y+6), as in the best kernel.
//   W conv: 14-col window (x4-5..x4+8), narrow side loads (1+4+4+1 floats).
__global__ __launch_bounds__(128, 6) void caxial_kernel(const float* __restrict__ x,
                                                        const float* __restrict__ wh,
                                                        const float* __restrict__ ww,
                                                        const float* __restrict__ rp,
                                                        float* __restrict__ out) {
    const int c  = blockIdx.z % CC;
    const int tx = threadIdx.x;                               // 0..63
    const int strip = blockIdx.y * 2 + threadIdx.y;           // 0..3
    const int x4 = tx * 4;
    const int y0 = strip * 64;
    const float* xc = x   + (size_t)blockIdx.z * (HH * WW);
    float*       oc = out + (size_t)blockIdx.z * (HH * WW);

    float rv = rp[0];
    if (rv < 1.0f) rv = 1.0f;

    float whv[KK], wwv[KK], fri[KK];
    int   k0i[KK];
    #pragma unroll
    for (int i = 0; i < KK; i++) {
        float ofr = (float)(i - 3) * rv;
        float fl  = floorf(ofr);
        k0i[i] = (int)fl + 5;                 // tap index base: dr = k - 5
        fri[i] = ofr - fl;
        whv[i] = wh[c * KK + i];
        wwv[i] = ww[c * KK + i];
    }
    // fast: all folded taps fall in k = 0..10  (r < 5/3)
    const bool fast = (k0i[0] >= 0) && (k0i[KK - 1] + 1 <= 10);

    if (fast) {
        // Fold 7 bilinear taps into 11 integer-offset weights (dc/dr = k - 5)
        unsigned long long cwh2[11];
        float cww[11];
        #pragma unroll
        for (int k = 0; k < 11; k++) {
            float sh = 0.f, sw = 0.f;
            #pragma unroll
            for (int i = 0; i < KK; i++) {
                if (k0i[i] == k)     { sh += whv[i] * (1.f - fri[i]); sw += wwv[i] * (1.f - fri[i]); }
                if (k0i[i] + 1 == k) { sh += whv[i] * fri[i];         sw += wwv[i] * fri[i]; }
            }
            cwh2[k] = pk2(sh, sh);
            cww[k]  = sw;
        }

        // 12-slot register ring; slot(row) = (row - y0 + 5) % 12.
        // Prologue: rows y0-5 .. y0+6 fill slots 0..11.
        ulonglong2 ring[12];
        #pragma unroll
        for (int t = -5; t <= 6; t++) {
            int row = y0 + t;
            ulonglong2 v = make_ulonglong2(0ull, 0ull);
            if (row >= 0)   // row < HH always true in prologue (y0 <= 192, t <= 6)
                v = *reinterpret_cast<const ulonglong2*>(xc + (size_t)row * WW + x4);
            ring[t + 5] = v;
        }

        // Side-load predicates: window cols x4-5 .. x4+8
        const bool eSL = (x4 >= 8);           // col  x4-5         (LDG.32)
        const bool eL1 = (x4 >= 4);           // cols x4-4..x4-1   (LDG.128)
        const bool eR1 = (tx <= 62);          // cols x4+4..x4+7   (LDG.128)
        const bool eSR = (tx <= 61);          // col  x4+8         (LDG.32)
        const float4 z4 = make_float4(0.f, 0.f, 0.f, 0.f);

        // Body for row y with ring phase u (compile-time in every call site)
        #define CAX_BODY(yy, uu)                                                          \
        {                                                                                 \
            const int y = (yy);                                                           \
            /* Ring prefetch: row y+6 -> slot (u+11)%12 (row y-6's slot, now dead) */     \
            {                                                                             \
                int row = y + 6;                                                          \
                ulonglong2 v = make_ulonglong2(0ull, 0ull);                               \
                if (row < HH)                                                             \
                    v = *reinterpret_cast<const ulonglong2*>(xc + (size_t)row * WW + x4); \
                ring[((uu) + 11) % 12] = v;                                               \
            }                                                                             \
            /* Side loads for row y (L1/L2 hits; consumed after H conv) */                \
            const float* rowp = xc + (size_t)y * WW;                                      \
            float  sl = eSL ? rowp[x4 - 5] : 0.f;                                         \
            float4 l1 = eL1 ? *reinterpret_cast<const float4*>(rowp + x4 - 4) : z4;       \
            float4 r1 = eR1 ? *reinterpret_cast<const float4*>(rowp + x4 + 4) : z4;       \
            float  sr = eSR ? rowp[x4 + 8] : 0.f;                                         \
                                                                                          \
            ulonglong2 ctr = ring[((uu) + 5) % 12];     /* row y */                       \
            float c0, c1, c2, c3;                                                         \
            upk2(ctr.x, c0, c1);                                                          \
            upk2(ctr.y, c2, c3);                                                          \
                                                                                          \
            unsigned long long acc01 = ctr.x;                                             \
            unsigned long long acc23 = ctr.y;                                             \
            _Pragma("unroll")                                                             \
            for (int k = 0; k < 11; k++) {              /* row y + (k-5) */               \
                ulonglong2 rv2 = ring[((uu) + k) % 12];                                   \
                fma2(acc01, cwh2[k], rv2.x);                                              \
                fma2(acc23, cwh2[k], rv2.y);                                              \
            }                                                                             \
            float a0, a1, a2, a3;                                                         \
            upk2(acc01, a0, a1);                                                          \
            upk2(acc23, a2, a3);                                                          \
                                                                                          \
            float win[14];                                                                \
            win[0]  = sl;                                                                 \
            win[1]  = l1.x; win[2]  = l1.y; win[3]  = l1.z; win[4]  = l1.w;               \
            win[5]  = c0;   win[6]  = c1;   win[7]  = c2;   win[8]  = c3;                 \
            win[9]  = r1.x; win[10] = r1.y; win[11] = r1.z; win[12] = r1.w;               \
            win[13] = sr;                                                                 \
            _Pragma("unroll")                                                             \
            for (int k = 0; k < 11; k++) {              /* col (x4+j)+(k-5) */            \
                float w = cww[k];                                                         \
                a0 += w * win[k];                                                         \
                a1 += w * win[k + 1];                                                     \
                a2 += w * win[k + 2];                                                     \
                a3 += w * win[k + 3];                                                     \
            }                                                                             \
            __stcs(reinterpret_cast<float4*>(oc + (size_t)y * WW + x4),                   \
                   make_float4(a0, a1, a2, a3));                                          \
        }

        #pragma unroll 1
        for (int g = 0; g < 5; g++) {                 // 5 groups of 12 rows
            int ybase = y0 + g * 12;
            #pragma unroll
            for (int u = 0; u < 12; u++) {
                CAX_BODY(ybase + u, u)
            }
        }
        {                                             // tail: 4 rows (60..63)
            int ybase = y0 + 60;                      // 60 % 12 == 0 -> same phases
            #pragma unroll
            for (int u = 0; u < 4; u++) {
                CAX_BODY(ybase + u, u)
            }
        }
        #undef CAX_BODY
    } else {
        // Generic path: direct 7-tap bilinear gather along both axes.
        #pragma unroll 1
        for (int yy = 0; yy < 64; yy++) {
            int y = y0 + yy;
            float acc[4];
            #pragma unroll
            for (int j = 0; j < 4; j++) acc[j] = xc[(size_t)y * WW + x4 + j];
            #pragma unroll
            for (int i = 0; i < KK; i++) {
                int   d  = k0i[i] - 5;
                float fr = fri[i];
                int r0 = y + d, r1 = r0 + 1;
                #pragma unroll
                for (int j = 0; j < 4; j++) {
                    int col = x4 + j;
                    float s0 = (r0 >= 0 && r0 < HH) ? xc[(size_t)r0 * WW + col] : 0.f;
                    float s1 = (r1 >= 0 && r1 < HH) ? xc[(size_t)r1 * WW + col] : 0.f;
                    acc[j] += whv[i] * (s0 * (1.f - fr) + s1 * fr);
                    int c0i = col + d, c1i = c0i + 1;
                    float t0 = (c0i >= 0 && c0i < WW) ? xc[(size_t)y * WW + c0i] : 0.f;
                    float t1 = (c1i >= 0 && c1i < WW) ? xc[(size_t)y * WW + c1i] : 0.f;
                    acc[j] += wwv[i] * (t0 * (1.f - fr) + t1 * fr);
                }
            }
            #pragma unroll
            for (int j = 0; j < 4; j++) oc[(size_t)y * WW + x4 + j] = acc[j];
        }
    }
}

extern "C" void kernel_launch(void* const* d_in, const int* in_sizes, int n_in,
                              void* d_out, int out_size) {
    const float* x  = (const float*)d_in[0];
    const float* wh = (const float*)d_in[1];
    const float* ww = (const float*)d_in[2];
    const float* r  = (const float*)d_in[3];
    float* out = (float*)d_out;

    int nimg = in_sizes[0] / (HH * WW);   // B*C = 768

    dim3 blk(64, 2, 1);
    dim3 grd(1, 2, nimg);
    caxial_kernel<<<grd, blk>>>(x, wh, ww, r, out);
}